// round 1
// baseline (speedup 1.0000x reference)
#include <cuda_runtime.h>
#include <cuda_bf16.h>
#include <math.h>

#define BATCH 2
#define SEQ   2048
#define DIM   1024
#define NH    16
#define DHD   64
#define MROWS (BATCH*SEQ)   // 4096

// ---------------- scratch (device globals: allocation-free) ----------------
__device__ float g_Q[(size_t)MROWS * DIM];
__device__ float g_K[(size_t)MROWS * DIM];
__device__ float g_V[(size_t)MROWS * DIM];
__device__ float g_C[(size_t)MROWS * DIM];

// ---------------- fp32 tiled GEMM: C = A[M,K] @ W[K,N] + bias --------------
// BM=128, BN=64, BK=16, 256 threads, each thread computes 8x4.
__global__ __launch_bounds__(256) void gemm_bias_kernel(
    const float* __restrict__ A, const float* __restrict__ W,
    const float* __restrict__ bias, float* __restrict__ C,
    int M, int N, int K)
{
    __shared__ float As[16][129];   // stored transposed: As[k][row]
    __shared__ float Bs[16][65];

    const int tid = threadIdx.x;
    const int ty  = tid >> 4;       // 0..15  -> 8 rows each
    const int tx  = tid & 15;       // 0..15  -> 4 cols each
    const int rowBase = blockIdx.y * 128;
    const int colBase = blockIdx.x * 64;

    float acc[8][4];
#pragma unroll
    for (int i = 0; i < 8; i++)
#pragma unroll
        for (int j = 0; j < 4; j++) acc[i][j] = 0.f;

    for (int k0 = 0; k0 < K; k0 += 16) {
        // load A tile 128x16 (transposed into smem)
#pragma unroll
        for (int i = 0; i < 8; i++) {
            int idx = tid + i * 256;
            int ar = idx >> 4, ac = idx & 15;
            As[ac][ar] = A[(size_t)(rowBase + ar) * K + (k0 + ac)];
        }
        // load W tile 16x64
#pragma unroll
        for (int i = 0; i < 4; i++) {
            int idx = tid + i * 256;
            int br = idx >> 6, bc = idx & 63;
            Bs[br][bc] = W[(size_t)(k0 + br) * N + (colBase + bc)];
        }
        __syncthreads();

#pragma unroll
        for (int k = 0; k < 16; k++) {
            float ra[8], rb[4];
#pragma unroll
            for (int i = 0; i < 8; i++) ra[i] = As[k][ty * 8 + i];
#pragma unroll
            for (int j = 0; j < 4; j++) rb[j] = Bs[k][tx * 4 + j];
#pragma unroll
            for (int i = 0; i < 8; i++)
#pragma unroll
                for (int j = 0; j < 4; j++)
                    acc[i][j] = fmaf(ra[i], rb[j], acc[i][j]);
        }
        __syncthreads();
    }

#pragma unroll
    for (int j = 0; j < 4; j++) {
        float bv = bias[colBase + tx * 4 + j];
#pragma unroll
        for (int i = 0; i < 8; i++) {
            C[(size_t)(rowBase + ty * 8 + i) * N + (colBase + tx * 4 + j)] =
                acc[i][j] + bv;
        }
    }
}

// ---------------- flash attention -----------------------------------------
// One CTA per (batch, head, 64-row Q tile). Streaming softmax over 32-key
// K/V tiles; K and V share one smem buffer. 256 threads = 16x16:
//   scores: thread owns 4 q-rows x 2 key-cols; PV acc: 4 q-rows x 4 dims.
__global__ __launch_bounds__(256) void flash_kernel(
    const float* __restrict__ Q, const float* __restrict__ K,
    const float* __restrict__ V, const float* __restrict__ mask,
    float* __restrict__ C)
{
    __shared__ float Qs[64][65];
    __shared__ float KVs[32][65];
    __shared__ float Ps[64][33];
    __shared__ float maskS[32];

    const int b  = blockIdx.z;
    const int h  = blockIdx.y;
    const int q0 = blockIdx.x * 64;
    const int tid = threadIdx.x;
    const int ty = tid >> 4, tx = tid & 15;
    const float scale = 0.125f;                // 1/sqrt(64)

    const size_t base = ((size_t)b * SEQ) * DIM + (size_t)h * DHD;

    // load Q tile 64x64
#pragma unroll
    for (int i = 0; i < 16; i++) {
        int idx = tid + i * 256;
        int r = idx >> 6, c = idx & 63;
        Qs[r][c] = Q[base + (size_t)(q0 + r) * DIM + c];
    }

    float m[4], l[4], acc[4][4];
#pragma unroll
    for (int i = 0; i < 4; i++) {
        m[i] = -1e30f; l[i] = 0.f;
#pragma unroll
        for (int j = 0; j < 4; j++) acc[i][j] = 0.f;
    }

    for (int kt = 0; kt < SEQ; kt += 32) {
        // ---- load K tile 32x64 into KVs ----
#pragma unroll
        for (int i = 0; i < 8; i++) {
            int idx = tid + i * 256;
            int r = idx >> 6, c = idx & 63;
            KVs[r][c] = K[base + (size_t)(kt + r) * DIM + c];
        }
        if (tid < 32) maskS[tid] = mask[b * SEQ + kt + tid];
        __syncthreads();

        // ---- scores 64x32: thread -> rows ty*4+i, cols tx*2+j ----
        float s[4][2];
#pragma unroll
        for (int i = 0; i < 4; i++) { s[i][0] = 0.f; s[i][1] = 0.f; }
#pragma unroll
        for (int d = 0; d < 64; d++) {
            float qv[4], kv[2];
#pragma unroll
            for (int i = 0; i < 4; i++) qv[i] = Qs[ty * 4 + i][d];
#pragma unroll
            for (int j = 0; j < 2; j++) kv[j] = KVs[tx * 2 + j][d];
#pragma unroll
            for (int i = 0; i < 4; i++)
#pragma unroll
                for (int j = 0; j < 2; j++)
                    s[i][j] = fmaf(qv[i], kv[j], s[i][j]);
        }
#pragma unroll
        for (int i = 0; i < 4; i++)
#pragma unroll
            for (int j = 0; j < 2; j++)
                s[i][j] = s[i][j] * scale - 1e6f * (1.f - maskS[tx * 2 + j]);

        // ---- online softmax update ----
        float p[4][2];
#pragma unroll
        for (int i = 0; i < 4; i++) {
            float rmax = fmaxf(s[i][0], s[i][1]);
#pragma unroll
            for (int off = 1; off < 16; off <<= 1)
                rmax = fmaxf(rmax, __shfl_xor_sync(0xffffffffu, rmax, off));
            float newm = fmaxf(m[i], rmax);
            float fac  = __expf(m[i] - newm);
            p[i][0] = __expf(s[i][0] - newm);
            p[i][1] = __expf(s[i][1] - newm);
            float rsum = p[i][0] + p[i][1];
#pragma unroll
            for (int off = 1; off < 16; off <<= 1)
                rsum += __shfl_xor_sync(0xffffffffu, rsum, off);
            l[i] = l[i] * fac + rsum;
            m[i] = newm;
#pragma unroll
            for (int j = 0; j < 4; j++) acc[i][j] *= fac;
        }

        // ---- stash P, then reuse KVs buffer for V ----
#pragma unroll
        for (int i = 0; i < 4; i++) {
            Ps[ty * 4 + i][tx * 2 + 0] = p[i][0];
            Ps[ty * 4 + i][tx * 2 + 1] = p[i][1];
        }
        __syncthreads();            // everyone done with K reads + P written
#pragma unroll
        for (int i = 0; i < 8; i++) {
            int idx = tid + i * 256;
            int r = idx >> 6, c = idx & 63;
            KVs[r][c] = V[base + (size_t)(kt + r) * DIM + c];
        }
        __syncthreads();

        // ---- acc += P @ V : thread -> rows ty*4+i, dims tx*4+j ----
#pragma unroll
        for (int k = 0; k < 32; k++) {
            float pv[4], vv[4];
#pragma unroll
            for (int i = 0; i < 4; i++) pv[i] = Ps[ty * 4 + i][k];
#pragma unroll
            for (int j = 0; j < 4; j++) vv[j] = KVs[k][tx * 4 + j];
#pragma unroll
            for (int i = 0; i < 4; i++)
#pragma unroll
                for (int j = 0; j < 4; j++)
                    acc[i][j] = fmaf(pv[i], vv[j], acc[i][j]);
        }
        __syncthreads();            // before next tile overwrites KVs/Ps
    }

    // ---- epilogue: ctx = acc / l ----
#pragma unroll
    for (int i = 0; i < 4; i++) {
        float inv = 1.f / l[i];
#pragma unroll
        for (int j = 0; j < 4; j++) {
            C[base + (size_t)(q0 + ty * 4 + i) * DIM + (tx * 4 + j)] =
                acc[i][j] * inv;
        }
    }
}

// ---------------- launch ----------------------------------------------------
extern "C" void kernel_launch(void* const* d_in, const int* in_sizes, int n_in,
                              void* d_out, int out_size)
{
    const float* X    = (const float*)d_in[0];
    const float* mask = (const float*)d_in[1];
    const float* Wq   = (const float*)d_in[2];
    const float* bq   = (const float*)d_in[3];
    const float* Wk   = (const float*)d_in[4];
    const float* bk   = (const float*)d_in[5];
    const float* Wv   = (const float*)d_in[6];
    const float* bv   = (const float*)d_in[7];
    const float* Wo   = (const float*)d_in[8];
    const float* bo   = (const float*)d_in[9];
    float* out = (float*)d_out;

    float *Q, *K, *V, *C;
    cudaGetSymbolAddress((void**)&Q, g_Q);
    cudaGetSymbolAddress((void**)&K, g_K);
    cudaGetSymbolAddress((void**)&V, g_V);
    cudaGetSymbolAddress((void**)&C, g_C);

    dim3 ggrid(DIM / 64, MROWS / 128);   // (16, 32)
    gemm_bias_kernel<<<ggrid, 256>>>(X, Wq, bq, Q, MROWS, DIM, DIM);
    gemm_bias_kernel<<<ggrid, 256>>>(X, Wk, bk, K, MROWS, DIM, DIM);
    gemm_bias_kernel<<<ggrid, 256>>>(X, Wv, bv, V, MROWS, DIM, DIM);

    dim3 fgrid(SEQ / 64, NH, BATCH);     // (32, 16, 2)
    flash_kernel<<<fgrid, 256>>>(Q, K, V, mask, C);

    gemm_bias_kernel<<<ggrid, 256>>>(C, Wo, bo, out, MROWS, DIM, DIM);
}

// round 2
// speedup vs baseline: 2.5796x; 2.5796x over previous
#include <cuda_runtime.h>
#include <cuda_fp16.h>
#include <math.h>
#include <stdint.h>

#define BATCH 2
#define SEQ   2048
#define DIM   1024
#define NH    16
#define DHD   64
#define MROWS (BATCH*SEQ)   // 4096

// ---------------- scratch (device globals: allocation-free) ----------------
__device__ float g_Q[(size_t)MROWS * DIM];
__device__ float g_K[(size_t)MROWS * DIM];
__device__ float g_V[(size_t)MROWS * DIM];
__device__ float g_C[(size_t)MROWS * DIM];

// ---------------- mma / ldmatrix helpers -----------------------------------
__device__ __forceinline__ uint32_t smem_u32(const void* p) {
    return (uint32_t)__cvta_generic_to_shared(p);
}
__device__ __forceinline__ void ldm_x4(uint32_t& r0, uint32_t& r1, uint32_t& r2,
                                       uint32_t& r3, uint32_t addr) {
    asm volatile("ldmatrix.sync.aligned.m8n8.x4.shared.b16 {%0,%1,%2,%3}, [%4];"
                 : "=r"(r0), "=r"(r1), "=r"(r2), "=r"(r3) : "r"(addr));
}
__device__ __forceinline__ void ldm_x2(uint32_t& r0, uint32_t& r1, uint32_t addr) {
    asm volatile("ldmatrix.sync.aligned.m8n8.x2.shared.b16 {%0,%1}, [%2];"
                 : "=r"(r0), "=r"(r1) : "r"(addr));
}
__device__ __forceinline__ void ldm_x2t(uint32_t& r0, uint32_t& r1, uint32_t addr) {
    asm volatile("ldmatrix.sync.aligned.m8n8.x2.trans.shared.b16 {%0,%1}, [%2];"
                 : "=r"(r0), "=r"(r1) : "r"(addr));
}
__device__ __forceinline__ void mma16(float* d, const uint32_t* a, const uint32_t* b) {
    asm volatile("mma.sync.aligned.m16n8k16.row.col.f32.f16.f16.f32 "
                 "{%0,%1,%2,%3}, {%4,%5,%6,%7}, {%8,%9}, {%0,%1,%2,%3};"
                 : "+f"(d[0]), "+f"(d[1]), "+f"(d[2]), "+f"(d[3])
                 : "r"(a[0]), "r"(a[1]), "r"(a[2]), "r"(a[3]),
                   "r"(b[0]), "r"(b[1]));
}
__device__ __forceinline__ void split2(float x, __half& h, __half& l) {
    h = __float2half_rn(x);
    l = __float2half_rn(x - __half2float(h));
}

// ============================================================================
// GEMM: C[M,N] = A[M,K] @ W[K,N] + bias  (M=4096, N=K=1024)
// fp16 hi/lo split (3 MMAs), CTA tile 64x128, BK=32, 256 threads (8 warps).
// Warp grid 2x4, warp tile 32x32 -> 2 mtiles x 4 ntiles of m16n8.
// ============================================================================
#define GBM 64
#define GBN 128
#define GBK 32
#define APAD 40    // 32+8 halfs per A row
#define BPAD 136   // 128+8 halfs per B row

__global__ __launch_bounds__(256) void gemm16_kernel(
    const float* __restrict__ A, const float* __restrict__ W,
    const float* __restrict__ bias, float* __restrict__ C)
{
    __shared__ __half Ah[GBM][APAD], Al[GBM][APAD];
    __shared__ __half Bh[GBK][BPAD], Bl[GBK][BPAD];

    const int tid  = threadIdx.x;
    const int wid  = tid >> 5;
    const int lane = tid & 31;
    const int wrow = wid >> 2;        // 0..1
    const int wcol = wid & 3;         // 0..3
    const int rowBase = blockIdx.y * GBM;
    const int colBase = blockIdx.x * GBN;

    const int rr = lane & 7, g = lane >> 3;

    float acc[2][4][4];
#pragma unroll
    for (int mt = 0; mt < 2; mt++)
#pragma unroll
        for (int nt = 0; nt < 4; nt++)
#pragma unroll
            for (int e = 0; e < 4; e++) acc[mt][nt][e] = 0.f;

    for (int k0 = 0; k0 < DIM; k0 += GBK) {
        // ---- load + split A tile 64x32 ----
#pragma unroll
        for (int i = 0; i < 2; i++) {
            int idx = tid + i * 256;           // 512 float4
            int r = idx >> 3, c4 = (idx & 7) << 2;
            float4 v = *(const float4*)(A + (size_t)(rowBase + r) * DIM + k0 + c4);
            __half h, l;
            split2(v.x, h, l); Ah[r][c4+0] = h; Al[r][c4+0] = l;
            split2(v.y, h, l); Ah[r][c4+1] = h; Al[r][c4+1] = l;
            split2(v.z, h, l); Ah[r][c4+2] = h; Al[r][c4+2] = l;
            split2(v.w, h, l); Ah[r][c4+3] = h; Al[r][c4+3] = l;
        }
        // ---- load + split W tile 32x128 ----
#pragma unroll
        for (int i = 0; i < 4; i++) {
            int idx = tid + i * 256;           // 1024 float4
            int r = idx >> 5, c4 = (idx & 31) << 2;
            float4 v = *(const float4*)(W + (size_t)(k0 + r) * DIM + colBase + c4);
            __half h, l;
            split2(v.x, h, l); Bh[r][c4+0] = h; Bl[r][c4+0] = l;
            split2(v.y, h, l); Bh[r][c4+1] = h; Bl[r][c4+1] = l;
            split2(v.z, h, l); Bh[r][c4+2] = h; Bl[r][c4+2] = l;
            split2(v.w, h, l); Bh[r][c4+3] = h; Bl[r][c4+3] = l;
        }
        __syncthreads();

#pragma unroll
        for (int ks = 0; ks < 2; ks++) {
            const int kl = ks * 16;
            // A fragments (hi/lo) for 2 mtiles
            uint32_t ahf[2][4], alf[2][4];
#pragma unroll
            for (int mt = 0; mt < 2; mt++) {
                int m0 = wrow * 32 + mt * 16;
                int row = m0 + rr + ((g & 1) << 3);
                int col = kl + ((g >> 1) << 3);
                ldm_x4(ahf[mt][0], ahf[mt][1], ahf[mt][2], ahf[mt][3],
                       smem_u32(&Ah[row][col]));
                ldm_x4(alf[mt][0], alf[mt][1], alf[mt][2], alf[mt][3],
                       smem_u32(&Al[row][col]));
            }
            // B fragments (hi/lo) for 4 ntiles (trans: rows=k, cols=n)
            uint32_t bhf[4][2], blf[4][2];
#pragma unroll
            for (int nt = 0; nt < 4; nt++) {
                int n0 = wcol * 32 + nt * 8;
                int row = kl + rr + ((g & 1) << 3);
                ldm_x2t(bhf[nt][0], bhf[nt][1], smem_u32(&Bh[row][n0]));
                ldm_x2t(blf[nt][0], blf[nt][1], smem_u32(&Bl[row][n0]));
            }
#pragma unroll
            for (int mt = 0; mt < 2; mt++)
#pragma unroll
                for (int nt = 0; nt < 4; nt++) {
                    mma16(acc[mt][nt], ahf[mt], bhf[nt]);
                    mma16(acc[mt][nt], ahf[mt], blf[nt]);
                    mma16(acc[mt][nt], alf[mt], bhf[nt]);
                }
        }
        __syncthreads();
    }

    // ---- epilogue: + bias, fp32 store ----
#pragma unroll
    for (int mt = 0; mt < 2; mt++) {
        int r0 = rowBase + wrow * 32 + mt * 16 + (lane >> 2);
#pragma unroll
        for (int nt = 0; nt < 4; nt++) {
            int c0 = colBase + wcol * 32 + nt * 8 + ((lane & 3) << 1);
            float b0 = bias[c0], b1 = bias[c0 + 1];
            C[(size_t)r0 * DIM + c0]           = acc[mt][nt][0] + b0;
            C[(size_t)r0 * DIM + c0 + 1]       = acc[mt][nt][1] + b1;
            C[(size_t)(r0 + 8) * DIM + c0]     = acc[mt][nt][2] + b0;
            C[(size_t)(r0 + 8) * DIM + c0 + 1] = acc[mt][nt][3] + b1;
        }
    }
}

// ============================================================================
// Flash attention: CTA = (b, h, 64 q-rows), 128 threads (4 warps x 16 rows),
// 32-key tiles, fp16 hi/lo split MMAs; P stays in registers (score C-frag
// layout == PV A-frag layout for m16n8k16).
// ============================================================================
#define FPAD 72    // 64+8 halfs per row

__global__ __launch_bounds__(128) void flash16_kernel(
    const float* __restrict__ Q, const float* __restrict__ K,
    const float* __restrict__ V, const float* __restrict__ mask,
    float* __restrict__ C)
{
    __shared__ __half Qh[64][FPAD], Ql[64][FPAD];
    __shared__ __half Kh[32][FPAD], Kl[32][FPAD];
    __shared__ __half Vh[32][FPAD], Vl[32][FPAD];
    __shared__ float  maskS[32];

    const int b   = blockIdx.z;
    const int h   = blockIdx.y;
    const int q0  = blockIdx.x * 64;
    const int tid = threadIdx.x;
    const int wid = tid >> 5;
    const int lane = tid & 31;
    const int rr = lane & 7, g = lane >> 3;
    const float scale = 0.125f;

    const size_t base = ((size_t)b * SEQ) * DIM + (size_t)h * DHD;

    // ---- load + split Q tile 64x64 ----
#pragma unroll
    for (int i = 0; i < 8; i++) {
        int idx = tid + i * 128;               // 1024 float4
        int r = idx >> 4, c4 = (idx & 15) << 2;
        float4 v = *(const float4*)(Q + base + (size_t)(q0 + r) * DIM + c4);
        __half hh, hl;
        split2(v.x, hh, hl); Qh[r][c4+0] = hh; Ql[r][c4+0] = hl;
        split2(v.y, hh, hl); Qh[r][c4+1] = hh; Ql[r][c4+1] = hl;
        split2(v.z, hh, hl); Qh[r][c4+2] = hh; Ql[r][c4+2] = hl;
        split2(v.w, hh, hl); Qh[r][c4+3] = hh; Ql[r][c4+3] = hl;
    }

    float m0r = -1e30f, m1r = -1e30f, l0r = 0.f, l1r = 0.f;
    float ctx[8][4];
#pragma unroll
    for (int nt = 0; nt < 8; nt++)
#pragma unroll
        for (int e = 0; e < 4; e++) ctx[nt][e] = 0.f;

    const int m0 = wid * 16;
    // precompute A-frag row/col (relative) for Q: row = m0+rr+((g&1)<<3), col offset (g>>1)<<3
    const int qrow = m0 + rr + ((g & 1) << 3);
    const int qcoff = (g >> 1) << 3;

    for (int kt = 0; kt < SEQ; kt += 32) {
        __syncthreads();   // prev iteration reads done
        // ---- load + split K and V tiles 32x64 ----
#pragma unroll
        for (int i = 0; i < 4; i++) {
            int idx = tid + i * 128;           // 512 float4
            int r = idx >> 4, c4 = (idx & 15) << 2;
            float4 v = *(const float4*)(K + base + (size_t)(kt + r) * DIM + c4);
            __half hh, hl;
            split2(v.x, hh, hl); Kh[r][c4+0] = hh; Kl[r][c4+0] = hl;
            split2(v.y, hh, hl); Kh[r][c4+1] = hh; Kl[r][c4+1] = hl;
            split2(v.z, hh, hl); Kh[r][c4+2] = hh; Kl[r][c4+2] = hl;
            split2(v.w, hh, hl); Kh[r][c4+3] = hh; Kl[r][c4+3] = hl;
        }
#pragma unroll
        for (int i = 0; i < 4; i++) {
            int idx = tid + i * 128;
            int r = idx >> 4, c4 = (idx & 15) << 2;
            float4 v = *(const float4*)(V + base + (size_t)(kt + r) * DIM + c4);
            __half hh, hl;
            split2(v.x, hh, hl); Vh[r][c4+0] = hh; Vl[r][c4+0] = hl;
            split2(v.y, hh, hl); Vh[r][c4+1] = hh; Vl[r][c4+1] = hl;
            split2(v.z, hh, hl); Vh[r][c4+2] = hh; Vl[r][c4+2] = hl;
            split2(v.w, hh, hl); Vh[r][c4+3] = hh; Vl[r][c4+3] = hl;
        }
        if (tid < 32) maskS[tid] = mask[b * SEQ + kt + tid];
        __syncthreads();

        // ---- scores: S[16 x 32] per warp, k = d = 64 ----
        float s[4][4];
#pragma unroll
        for (int nt = 0; nt < 4; nt++)
#pragma unroll
            for (int e = 0; e < 4; e++) s[nt][e] = 0.f;

#pragma unroll
        for (int ks = 0; ks < 4; ks++) {
            const int kl = ks * 16;
            uint32_t qah[4], qal[4];
            ldm_x4(qah[0], qah[1], qah[2], qah[3], smem_u32(&Qh[qrow][kl + qcoff]));
            ldm_x4(qal[0], qal[1], qal[2], qal[3], smem_u32(&Ql[qrow][kl + qcoff]));
#pragma unroll
            for (int nt = 0; nt < 4; nt++) {
                // non-trans: rows = keys, cols = d; tile1 at d+8
                int krow = nt * 8 + rr;
                int kcol = kl + ((g & 1) << 3);
                uint32_t kbh[2], kbl[2];
                ldm_x2(kbh[0], kbh[1], smem_u32(&Kh[krow][kcol]));
                ldm_x2(kbl[0], kbl[1], smem_u32(&Kl[krow][kcol]));
                mma16(s[nt], qah, kbh);
                mma16(s[nt], qah, kbl);
                mma16(s[nt], qal, kbh);
            }
        }

        // ---- scale + mask ----
#pragma unroll
        for (int nt = 0; nt < 4; nt++) {
            int c = nt * 8 + ((lane & 3) << 1);
            float mv0 = -1e6f * (1.f - maskS[c]);
            float mv1 = -1e6f * (1.f - maskS[c + 1]);
            s[nt][0] = s[nt][0] * scale + mv0;
            s[nt][1] = s[nt][1] * scale + mv1;
            s[nt][2] = s[nt][2] * scale + mv0;
            s[nt][3] = s[nt][3] * scale + mv1;
        }

        // ---- online softmax (rows lane/4 and lane/4+8) ----
        float rmax0 = -1e30f, rmax1 = -1e30f;
#pragma unroll
        for (int nt = 0; nt < 4; nt++) {
            rmax0 = fmaxf(rmax0, fmaxf(s[nt][0], s[nt][1]));
            rmax1 = fmaxf(rmax1, fmaxf(s[nt][2], s[nt][3]));
        }
        rmax0 = fmaxf(rmax0, __shfl_xor_sync(0xffffffffu, rmax0, 1));
        rmax0 = fmaxf(rmax0, __shfl_xor_sync(0xffffffffu, rmax0, 2));
        rmax1 = fmaxf(rmax1, __shfl_xor_sync(0xffffffffu, rmax1, 1));
        rmax1 = fmaxf(rmax1, __shfl_xor_sync(0xffffffffu, rmax1, 2));
        float newm0 = fmaxf(m0r, rmax0), newm1 = fmaxf(m1r, rmax1);
        float fac0 = __expf(m0r - newm0), fac1 = __expf(m1r - newm1);
        m0r = newm0; m1r = newm1;

        float p[4][4];
        float rsum0 = 0.f, rsum1 = 0.f;
#pragma unroll
        for (int nt = 0; nt < 4; nt++) {
            p[nt][0] = __expf(s[nt][0] - newm0);
            p[nt][1] = __expf(s[nt][1] - newm0);
            p[nt][2] = __expf(s[nt][2] - newm1);
            p[nt][3] = __expf(s[nt][3] - newm1);
            rsum0 += p[nt][0] + p[nt][1];
            rsum1 += p[nt][2] + p[nt][3];
        }
        rsum0 += __shfl_xor_sync(0xffffffffu, rsum0, 1);
        rsum0 += __shfl_xor_sync(0xffffffffu, rsum0, 2);
        rsum1 += __shfl_xor_sync(0xffffffffu, rsum1, 1);
        rsum1 += __shfl_xor_sync(0xffffffffu, rsum1, 2);
        l0r = l0r * fac0 + rsum0;
        l1r = l1r * fac1 + rsum1;

#pragma unroll
        for (int nt = 0; nt < 8; nt++) {
            ctx[nt][0] *= fac0; ctx[nt][1] *= fac0;
            ctx[nt][2] *= fac1; ctx[nt][3] *= fac1;
        }

        // ---- pack P into A-fragments (C-frag layout == A-frag layout) ----
        uint32_t pah[2][4], pal[2][4];
#pragma unroll
        for (int kb = 0; kb < 2; kb++) {
            int t0 = kb * 2, t1 = kb * 2 + 1;
            __half h0, l0, h1, l1;
            split2(p[t0][0], h0, l0); split2(p[t0][1], h1, l1);
            pah[kb][0] = (uint32_t)__half_as_ushort(h0) | ((uint32_t)__half_as_ushort(h1) << 16);
            pal[kb][0] = (uint32_t)__half_as_ushort(l0) | ((uint32_t)__half_as_ushort(l1) << 16);
            split2(p[t0][2], h0, l0); split2(p[t0][3], h1, l1);
            pah[kb][1] = (uint32_t)__half_as_ushort(h0) | ((uint32_t)__half_as_ushort(h1) << 16);
            pal[kb][1] = (uint32_t)__half_as_ushort(l0) | ((uint32_t)__half_as_ushort(l1) << 16);
            split2(p[t1][0], h0, l0); split2(p[t1][1], h1, l1);
            pah[kb][2] = (uint32_t)__half_as_ushort(h0) | ((uint32_t)__half_as_ushort(h1) << 16);
            pal[kb][2] = (uint32_t)__half_as_ushort(l0) | ((uint32_t)__half_as_ushort(l1) << 16);
            split2(p[t1][2], h0, l0); split2(p[t1][3], h1, l1);
            pah[kb][3] = (uint32_t)__half_as_ushort(h0) | ((uint32_t)__half_as_ushort(h1) << 16);
            pal[kb][3] = (uint32_t)__half_as_ushort(l0) | ((uint32_t)__half_as_ushort(l1) << 16);
        }

        // ---- ctx += P @ V ----
#pragma unroll
        for (int kb = 0; kb < 2; kb++) {
            int vrow = kb * 16 + rr + ((g & 1) << 3);   // rows = keys (trans)
#pragma unroll
            for (int nt = 0; nt < 8; nt++) {
                int n0 = nt * 8;
                uint32_t vbh[2], vbl[2];
                ldm_x2t(vbh[0], vbh[1], smem_u32(&Vh[vrow][n0]));
                ldm_x2t(vbl[0], vbl[1], smem_u32(&Vl[vrow][n0]));
                mma16(ctx[nt], pah[kb], vbh);
                mma16(ctx[nt], pah[kb], vbl);
                mma16(ctx[nt], pal[kb], vbh);
            }
        }
    }

    // ---- epilogue: ctx / l -> C ----
    float inv0 = 1.f / l0r, inv1 = 1.f / l1r;
    int r0 = q0 + m0 + (lane >> 2);
#pragma unroll
    for (int nt = 0; nt < 8; nt++) {
        int c0 = nt * 8 + ((lane & 3) << 1);
        C[base + (size_t)r0 * DIM + c0]           = ctx[nt][0] * inv0;
        C[base + (size_t)r0 * DIM + c0 + 1]       = ctx[nt][1] * inv0;
        C[base + (size_t)(r0 + 8) * DIM + c0]     = ctx[nt][2] * inv1;
        C[base + (size_t)(r0 + 8) * DIM + c0 + 1] = ctx[nt][3] * inv1;
    }
}

// ---------------- launch ----------------------------------------------------
extern "C" void kernel_launch(void* const* d_in, const int* in_sizes, int n_in,
                              void* d_out, int out_size)
{
    const float* X    = (const float*)d_in[0];
    const float* mask = (const float*)d_in[1];
    const float* Wq   = (const float*)d_in[2];
    const float* bq   = (const float*)d_in[3];
    const float* Wk   = (const float*)d_in[4];
    const float* bk   = (const float*)d_in[5];
    const float* Wv   = (const float*)d_in[6];
    const float* bv   = (const float*)d_in[7];
    const float* Wo   = (const float*)d_in[8];
    const float* bo   = (const float*)d_in[9];
    float* out = (float*)d_out;

    float *Q, *K, *V, *C;
    cudaGetSymbolAddress((void**)&Q, g_Q);
    cudaGetSymbolAddress((void**)&K, g_K);
    cudaGetSymbolAddress((void**)&V, g_V);
    cudaGetSymbolAddress((void**)&C, g_C);

    dim3 ggrid(DIM / GBN, MROWS / GBM);   // (8, 64)
    gemm16_kernel<<<ggrid, 256>>>(X, Wq, bq, Q);
    gemm16_kernel<<<ggrid, 256>>>(X, Wk, bk, K);
    gemm16_kernel<<<ggrid, 256>>>(X, Wv, bv, V);

    dim3 fgrid(SEQ / 64, NH, BATCH);      // (32, 16, 2)
    flash16_kernel<<<fgrid, 128>>>(Q, K, V, mask, C);

    gemm16_kernel<<<ggrid, 256>>>(C, Wo, bo, out);
}

// round 3
// speedup vs baseline: 3.0070x; 1.1657x over previous
#include <cuda_runtime.h>
#include <cuda_fp16.h>
#include <math.h>
#include <stdint.h>

#define BATCH 2
#define SEQ   2048
#define DIM   1024
#define NH    16
#define DHD   64
#define MROWS (BATCH*SEQ)   // 4096

// ---------------- scratch (device globals: allocation-free) ----------------
__device__ __half g_Xh[(size_t)MROWS * DIM], g_Xl[(size_t)MROWS * DIM];
__device__ __half g_Wqh[(size_t)DIM * DIM], g_Wql[(size_t)DIM * DIM];
__device__ __half g_Wkh[(size_t)DIM * DIM], g_Wkl[(size_t)DIM * DIM];
__device__ __half g_Wvh[(size_t)DIM * DIM], g_Wvl[(size_t)DIM * DIM];
__device__ __half g_Woh[(size_t)DIM * DIM], g_Wol[(size_t)DIM * DIM];
__device__ __half g_Qh[(size_t)MROWS * DIM], g_Ql[(size_t)MROWS * DIM];
__device__ __half g_Kh[(size_t)MROWS * DIM], g_Kl[(size_t)MROWS * DIM];
__device__ __half g_Vh[(size_t)MROWS * DIM], g_Vl[(size_t)MROWS * DIM];
__device__ __half g_Ch[(size_t)MROWS * DIM], g_Cl[(size_t)MROWS * DIM];

// ---------------- helpers ---------------------------------------------------
__device__ __forceinline__ uint32_t smem_u32(const void* p) {
    return (uint32_t)__cvta_generic_to_shared(p);
}
__device__ __forceinline__ void cp16(void* dst, const void* src) {
    asm volatile("cp.async.cg.shared.global [%0], [%1], 16;"
                 :: "r"(smem_u32(dst)), "l"(src));
}
#define CP_COMMIT() asm volatile("cp.async.commit_group;")
#define CP_WAIT(n)  asm volatile("cp.async.wait_group %0;" :: "n"(n))

__device__ __forceinline__ void ldm_x4(uint32_t* r, uint32_t addr) {
    asm volatile("ldmatrix.sync.aligned.m8n8.x4.shared.b16 {%0,%1,%2,%3}, [%4];"
                 : "=r"(r[0]), "=r"(r[1]), "=r"(r[2]), "=r"(r[3]) : "r"(addr));
}
__device__ __forceinline__ void ldm_x4t(uint32_t* r, uint32_t addr) {
    asm volatile("ldmatrix.sync.aligned.m8n8.x4.trans.shared.b16 {%0,%1,%2,%3}, [%4];"
                 : "=r"(r[0]), "=r"(r[1]), "=r"(r[2]), "=r"(r[3]) : "r"(addr));
}
__device__ __forceinline__ void mma16(float* d, const uint32_t* a, const uint32_t* b) {
    asm volatile("mma.sync.aligned.m16n8k16.row.col.f32.f16.f16.f32 "
                 "{%0,%1,%2,%3}, {%4,%5,%6,%7}, {%8,%9}, {%0,%1,%2,%3};"
                 : "+f"(d[0]), "+f"(d[1]), "+f"(d[2]), "+f"(d[3])
                 : "r"(a[0]), "r"(a[1]), "r"(a[2]), "r"(a[3]),
                   "r"(b[0]), "r"(b[1]));
}
__device__ __forceinline__ void split2(float x, __half& h, __half& l) {
    h = __float2half_rn(x);
    l = __float2half_rn(x - __half2float(h));
}

// ---------------- split: fp32 -> (hi, lo) fp16 ------------------------------
__global__ __launch_bounds__(256) void split_kernel(
    const float4* __restrict__ src, __half2* __restrict__ hi,
    __half2* __restrict__ lo, int n4)
{
    int i = blockIdx.x * 256 + threadIdx.x;
    if (i >= n4) return;
    float4 v = src[i];
    __half h0, l0, h1, l1;
    split2(v.x, h0, l0); split2(v.y, h1, l1);
    hi[2 * i]     = __halves2half2(h0, h1);
    lo[2 * i]     = __halves2half2(l0, l1);
    split2(v.z, h0, l0); split2(v.w, h1, l1);
    hi[2 * i + 1] = __halves2half2(h0, h1);
    lo[2 * i + 1] = __halves2half2(l0, l1);
}

// ============================================================================
// GEMM on pre-split halves: C = A[M,K] @ W[K,N] (+bias)*scale
// CTA 64x128, BK=32, 256 threads, warp 32x32, fp16 hi/lo 3-MMA emulation.
// ============================================================================
#define GBM 64
#define GBN 128
#define GBK 32
#define APAD 40
#define BPAD 136

template<bool SPLIT_OUT>
__global__ __launch_bounds__(256) void gemmh_kernel(
    const __half* __restrict__ Ah_g, const __half* __restrict__ Al_g,
    const __half* __restrict__ Bh_g, const __half* __restrict__ Bl_g,
    const float* __restrict__ bias, float out_scale,
    float* __restrict__ Cf, __half* __restrict__ Ch_g, __half* __restrict__ Cl_g)
{
    __shared__ __align__(16) __half Ahs[GBM * APAD], Als[GBM * APAD];
    __shared__ __align__(16) __half Bhs[GBK * BPAD], Bls[GBK * BPAD];

    const int tid = threadIdx.x;
    const int wid = tid >> 5, lane = tid & 31;
    const int wrow = wid >> 2, wcol = wid & 3;
    const int rowBase = blockIdx.y * GBM;
    const int colBase = blockIdx.x * GBN;
    const int rr = lane & 7, g = lane >> 3;

    float acc[2][4][4];
#pragma unroll
    for (int mt = 0; mt < 2; mt++)
#pragma unroll
        for (int nt = 0; nt < 4; nt++)
#pragma unroll
            for (int e = 0; e < 4; e++) acc[mt][nt][e] = 0.f;

    for (int k0 = 0; k0 < DIM; k0 += GBK) {
        // A tile 64x32 (1 cp16 per thread per array)
        {
            int r = tid >> 2, c8 = (tid & 3) << 3;
            size_t go = (size_t)(rowBase + r) * DIM + k0 + c8;
            cp16(&Ahs[r * APAD + c8], Ah_g + go);
            cp16(&Als[r * APAD + c8], Al_g + go);
        }
        // B tile 32x128 (2 per thread per array)
#pragma unroll
        for (int i = 0; i < 2; i++) {
            int idx = tid + i * 256;
            int r = idx >> 4, c8 = (idx & 15) << 3;
            size_t go = (size_t)(k0 + r) * DIM + colBase + c8;
            cp16(&Bhs[r * BPAD + c8], Bh_g + go);
            cp16(&Bls[r * BPAD + c8], Bl_g + go);
        }
        CP_COMMIT(); CP_WAIT(0);
        __syncthreads();

#pragma unroll
        for (int ks = 0; ks < 2; ks++) {
            const int kl = ks * 16;
            uint32_t ahf[2][4], alf[2][4];
#pragma unroll
            for (int mt = 0; mt < 2; mt++) {
                int row = wrow * 32 + mt * 16 + rr + ((g & 1) << 3);
                int col = kl + ((g >> 1) << 3);
                ldm_x4(ahf[mt], smem_u32(&Ahs[row * APAD + col]));
                ldm_x4(alf[mt], smem_u32(&Als[row * APAD + col]));
            }
#pragma unroll
            for (int ntp = 0; ntp < 2; ntp++) {
                int brow = kl + rr + (((lane >> 3) & 1) << 3);
                int bcol = wcol * 32 + ntp * 16 + ((lane >> 4) << 3);
                uint32_t bh[4], bl[4];
                ldm_x4t(bh, smem_u32(&Bhs[brow * BPAD + bcol]));
                ldm_x4t(bl, smem_u32(&Bls[brow * BPAD + bcol]));
#pragma unroll
                for (int mt = 0; mt < 2; mt++) {
                    mma16(acc[mt][2 * ntp],     ahf[mt], bh);
                    mma16(acc[mt][2 * ntp],     ahf[mt], bl);
                    mma16(acc[mt][2 * ntp],     alf[mt], bh);
                    mma16(acc[mt][2 * ntp + 1], ahf[mt], bh + 2);
                    mma16(acc[mt][2 * ntp + 1], ahf[mt], bl + 2);
                    mma16(acc[mt][2 * ntp + 1], alf[mt], bh + 2);
                }
            }
        }
        __syncthreads();
    }

    // epilogue
#pragma unroll
    for (int mt = 0; mt < 2; mt++) {
        int r0 = rowBase + wrow * 32 + mt * 16 + (lane >> 2);
#pragma unroll
        for (int nt = 0; nt < 4; nt++) {
            int c0 = colBase + wcol * 32 + nt * 8 + ((lane & 3) << 1);
            float b0 = bias[c0], b1 = bias[c0 + 1];
            float v00 = (acc[mt][nt][0] + b0) * out_scale;
            float v01 = (acc[mt][nt][1] + b1) * out_scale;
            float v10 = (acc[mt][nt][2] + b0) * out_scale;
            float v11 = (acc[mt][nt][3] + b1) * out_scale;
            if (SPLIT_OUT) {
                __half h0, l0, h1, l1;
                split2(v00, h0, l0); split2(v01, h1, l1);
                *(__half2*)&Ch_g[(size_t)r0 * DIM + c0] = __halves2half2(h0, h1);
                *(__half2*)&Cl_g[(size_t)r0 * DIM + c0] = __halves2half2(l0, l1);
                split2(v10, h0, l0); split2(v11, h1, l1);
                *(__half2*)&Ch_g[(size_t)(r0 + 8) * DIM + c0] = __halves2half2(h0, h1);
                *(__half2*)&Cl_g[(size_t)(r0 + 8) * DIM + c0] = __halves2half2(l0, l1);
            } else {
                Cf[(size_t)r0 * DIM + c0]           = v00;
                Cf[(size_t)r0 * DIM + c0 + 1]       = v01;
                Cf[(size_t)(r0 + 8) * DIM + c0]     = v10;
                Cf[(size_t)(r0 + 8) * DIM + c0 + 1] = v11;
            }
        }
    }
}

// ============================================================================
// Flash attention: 256 threads, 128 q-rows/CTA (8 warps x 16 rows).
// Q frags preloaded to registers; Q smem reused as double-buffered K/V.
// Scale folded into Q upstream. fp16 hi/lo 3-MMA.
// ============================================================================
#define FPAD 72
#define KVOFF_KL 2304   // 32*FPAD
#define KVOFF_VH 4608
#define KVOFF_VL 6912

__global__ __launch_bounds__(256) void flash16_kernel(
    const __half* __restrict__ Qh_g, const __half* __restrict__ Ql_g,
    const __half* __restrict__ Kh_g, const __half* __restrict__ Kl_g,
    const __half* __restrict__ Vh_g, const __half* __restrict__ Vl_g,
    const float* __restrict__ mask,
    __half* __restrict__ Ch_g, __half* __restrict__ Cl_g)
{
    __shared__ __align__(16) __half fsm[2][128 * FPAD];   // Q staging, then KV x2
    __shared__ __align__(16) float maskS[2][32];

    const int b = blockIdx.z, h = blockIdx.y;
    const int q0 = blockIdx.x * 128;
    const int tid = threadIdx.x, wid = tid >> 5, lane = tid & 31;
    const int rr = lane & 7, g = lane >> 3;
    const size_t base = ((size_t)b * SEQ) * DIM + (size_t)h * DHD;

    // ---- stage Q (128x64 halfs, hi+lo), then preload fragments ----
#pragma unroll
    for (int i = 0; i < 4; i++) {
        int idx = tid + i * 256;
        int r = idx >> 3, c8 = (idx & 7) << 3;
        size_t go = base + (size_t)(q0 + r) * DIM + c8;
        cp16(&fsm[0][r * FPAD + c8], Qh_g + go);
        cp16(&fsm[1][r * FPAD + c8], Ql_g + go);
    }
    CP_COMMIT(); CP_WAIT(0);
    __syncthreads();

    const int m0 = wid * 16;
    const int qrow = m0 + rr + ((g & 1) << 3);
    const int qcoff = (g >> 1) << 3;
    uint32_t qfh[4][4], qfl[4][4];
#pragma unroll
    for (int ks = 0; ks < 4; ks++) {
        ldm_x4(qfh[ks], smem_u32(&fsm[0][qrow * FPAD + ks * 16 + qcoff]));
        ldm_x4(qfl[ks], smem_u32(&fsm[1][qrow * FPAD + ks * 16 + qcoff]));
    }
    __syncthreads();   // Q smem now reusable

    auto loadKV = [&](int buf, int kt) {
        __half* s = fsm[buf];
        int r = tid >> 3, c8 = (tid & 7) << 3;
        size_t go = base + (size_t)(kt + r) * DIM + c8;
        cp16(&s[          r * FPAD + c8], Kh_g + go);
        cp16(&s[KVOFF_KL + r * FPAD + c8], Kl_g + go);
        cp16(&s[KVOFF_VH + r * FPAD + c8], Vh_g + go);
        cp16(&s[KVOFF_VL + r * FPAD + c8], Vl_g + go);
        if (tid < 8) cp16(&maskS[buf][tid * 4], mask + (size_t)b * SEQ + kt + tid * 4);
    };

    float m0r = -1e30f, m1r = -1e30f, l0r = 0.f, l1r = 0.f;
    float ctx[8][4];
#pragma unroll
    for (int nt = 0; nt < 8; nt++)
#pragma unroll
        for (int e = 0; e < 4; e++) ctx[nt][e] = 0.f;

    loadKV(0, 0); CP_COMMIT();

#pragma unroll 1
    for (int t = 0; t < SEQ / 32; t++) {
        if (t < SEQ / 32 - 1) { loadKV((t + 1) & 1, (t + 1) * 32); CP_COMMIT(); }
        if (t < SEQ / 32 - 1) { CP_WAIT(1); } else { CP_WAIT(0); }
        __syncthreads();

        const __half* Ks = fsm[t & 1];
        const float*  mS = maskS[t & 1];

        // ---- scores S[16x32] ----
        float s[4][4];
#pragma unroll
        for (int nt = 0; nt < 4; nt++)
#pragma unroll
            for (int e = 0; e < 4; e++) s[nt][e] = 0.f;

#pragma unroll
        for (int ks = 0; ks < 4; ks++) {
#pragma unroll
            for (int ntp = 0; ntp < 2; ntp++) {
                int krow = ntp * 16 + ((lane >> 4) << 3) + rr;
                int kcol = ks * 16 + (((lane >> 3) & 1) << 3);
                uint32_t kh[4], kl[4];
                ldm_x4(kh, smem_u32(&Ks[krow * FPAD + kcol]));
                ldm_x4(kl, smem_u32(&Ks[KVOFF_KL + krow * FPAD + kcol]));
                mma16(s[2 * ntp],     qfh[ks], kh);
                mma16(s[2 * ntp],     qfh[ks], kl);
                mma16(s[2 * ntp],     qfl[ks], kh);
                mma16(s[2 * ntp + 1], qfh[ks], kh + 2);
                mma16(s[2 * ntp + 1], qfh[ks], kl + 2);
                mma16(s[2 * ntp + 1], qfl[ks], kh + 2);
            }
        }

        // ---- mask (scale already folded into Q) ----
#pragma unroll
        for (int nt = 0; nt < 4; nt++) {
            int c = nt * 8 + ((lane & 3) << 1);
            float mv0 = fmaf(mS[c],     1e6f, -1e6f);
            float mv1 = fmaf(mS[c + 1], 1e6f, -1e6f);
            s[nt][0] += mv0; s[nt][1] += mv1;
            s[nt][2] += mv0; s[nt][3] += mv1;
        }

        // ---- online softmax ----
        float rmax0 = -1e30f, rmax1 = -1e30f;
#pragma unroll
        for (int nt = 0; nt < 4; nt++) {
            rmax0 = fmaxf(rmax0, fmaxf(s[nt][0], s[nt][1]));
            rmax1 = fmaxf(rmax1, fmaxf(s[nt][2], s[nt][3]));
        }
        rmax0 = fmaxf(rmax0, __shfl_xor_sync(0xffffffffu, rmax0, 1));
        rmax0 = fmaxf(rmax0, __shfl_xor_sync(0xffffffffu, rmax0, 2));
        rmax1 = fmaxf(rmax1, __shfl_xor_sync(0xffffffffu, rmax1, 1));
        rmax1 = fmaxf(rmax1, __shfl_xor_sync(0xffffffffu, rmax1, 2));
        float newm0 = fmaxf(m0r, rmax0), newm1 = fmaxf(m1r, rmax1);
        float fac0 = __expf(m0r - newm0), fac1 = __expf(m1r - newm1);
        m0r = newm0; m1r = newm1;

        float p[4][4];
        float rsum0 = 0.f, rsum1 = 0.f;
#pragma unroll
        for (int nt = 0; nt < 4; nt++) {
            p[nt][0] = __expf(s[nt][0] - newm0);
            p[nt][1] = __expf(s[nt][1] - newm0);
            p[nt][2] = __expf(s[nt][2] - newm1);
            p[nt][3] = __expf(s[nt][3] - newm1);
            rsum0 += p[nt][0] + p[nt][1];
            rsum1 += p[nt][2] + p[nt][3];
        }
        rsum0 += __shfl_xor_sync(0xffffffffu, rsum0, 1);
        rsum0 += __shfl_xor_sync(0xffffffffu, rsum0, 2);
        rsum1 += __shfl_xor_sync(0xffffffffu, rsum1, 1);
        rsum1 += __shfl_xor_sync(0xffffffffu, rsum1, 2);
        l0r = l0r * fac0 + rsum0;
        l1r = l1r * fac1 + rsum1;

#pragma unroll
        for (int nt = 0; nt < 8; nt++) {
            ctx[nt][0] *= fac0; ctx[nt][1] *= fac0;
            ctx[nt][2] *= fac1; ctx[nt][3] *= fac1;
        }

        // ---- pack P (C-frag layout == A-frag layout) ----
        uint32_t pah[2][4], pal[2][4];
#pragma unroll
        for (int kb = 0; kb < 2; kb++) {
            int t0 = kb * 2, t1 = kb * 2 + 1;
            __half h0, l0, h1, l1;
            split2(p[t0][0], h0, l0); split2(p[t0][1], h1, l1);
            pah[kb][0] = (uint32_t)__half_as_ushort(h0) | ((uint32_t)__half_as_ushort(h1) << 16);
            pal[kb][0] = (uint32_t)__half_as_ushort(l0) | ((uint32_t)__half_as_ushort(l1) << 16);
            split2(p[t0][2], h0, l0); split2(p[t0][3], h1, l1);
            pah[kb][1] = (uint32_t)__half_as_ushort(h0) | ((uint32_t)__half_as_ushort(h1) << 16);
            pal[kb][1] = (uint32_t)__half_as_ushort(l0) | ((uint32_t)__half_as_ushort(l1) << 16);
            split2(p[t1][0], h0, l0); split2(p[t1][1], h1, l1);
            pah[kb][2] = (uint32_t)__half_as_ushort(h0) | ((uint32_t)__half_as_ushort(h1) << 16);
            pal[kb][2] = (uint32_t)__half_as_ushort(l0) | ((uint32_t)__half_as_ushort(l1) << 16);
            split2(p[t1][2], h0, l0); split2(p[t1][3], h1, l1);
            pah[kb][3] = (uint32_t)__half_as_ushort(h0) | ((uint32_t)__half_as_ushort(h1) << 16);
            pal[kb][3] = (uint32_t)__half_as_ushort(l0) | ((uint32_t)__half_as_ushort(l1) << 16);
        }

        // ---- ctx += P @ V ----
#pragma unroll
        for (int kb = 0; kb < 2; kb++) {
            int vrow = kb * 16 + rr + (((lane >> 3) & 1) << 3);
#pragma unroll
            for (int ntp = 0; ntp < 4; ntp++) {
                int vcol = ntp * 16 + ((lane >> 4) << 3);
                uint32_t vh[4], vl[4];
                ldm_x4t(vh, smem_u32(&Ks[KVOFF_VH + vrow * FPAD + vcol]));
                ldm_x4t(vl, smem_u32(&Ks[KVOFF_VL + vrow * FPAD + vcol]));
                mma16(ctx[2 * ntp],     pah[kb], vh);
                mma16(ctx[2 * ntp],     pah[kb], vl);
                mma16(ctx[2 * ntp],     pal[kb], vh);
                mma16(ctx[2 * ntp + 1], pah[kb], vh + 2);
                mma16(ctx[2 * ntp + 1], pah[kb], vl + 2);
                mma16(ctx[2 * ntp + 1], pal[kb], vh + 2);
            }
        }
        __syncthreads();
    }

    // ---- epilogue: ctx / l -> split halves ----
    float inv0 = 1.f / l0r, inv1 = 1.f / l1r;
    int r0 = q0 + m0 + (lane >> 2);
#pragma unroll
    for (int nt = 0; nt < 8; nt++) {
        int c0 = nt * 8 + ((lane & 3) << 1);
        __half h0, l0, h1, l1;
        split2(ctx[nt][0] * inv0, h0, l0); split2(ctx[nt][1] * inv0, h1, l1);
        *(__half2*)&Ch_g[base + (size_t)r0 * DIM + c0] = __halves2half2(h0, h1);
        *(__half2*)&Cl_g[base + (size_t)r0 * DIM + c0] = __halves2half2(l0, l1);
        split2(ctx[nt][2] * inv1, h0, l0); split2(ctx[nt][3] * inv1, h1, l1);
        *(__half2*)&Ch_g[base + (size_t)(r0 + 8) * DIM + c0] = __halves2half2(h0, h1);
        *(__half2*)&Cl_g[base + (size_t)(r0 + 8) * DIM + c0] = __halves2half2(l0, l1);
    }
}

// ---------------- launch ----------------------------------------------------
extern "C" void kernel_launch(void* const* d_in, const int* in_sizes, int n_in,
                              void* d_out, int out_size)
{
    const float* X    = (const float*)d_in[0];
    const float* mask = (const float*)d_in[1];
    const float* Wq   = (const float*)d_in[2];
    const float* bq   = (const float*)d_in[3];
    const float* Wk   = (const float*)d_in[4];
    const float* bk   = (const float*)d_in[5];
    const float* Wv   = (const float*)d_in[6];
    const float* bv   = (const float*)d_in[7];
    const float* Wo   = (const float*)d_in[8];
    const float* bo   = (const float*)d_in[9];
    float* out = (float*)d_out;

    __half *Xh, *Xl, *Wqh, *Wql, *Wkh, *Wkl, *Wvh, *Wvl, *Woh, *Wol;
    __half *Qh, *Ql, *Kh, *Kl, *Vh, *Vl, *Ch, *Cl;
    cudaGetSymbolAddress((void**)&Xh, g_Xh);   cudaGetSymbolAddress((void**)&Xl, g_Xl);
    cudaGetSymbolAddress((void**)&Wqh, g_Wqh); cudaGetSymbolAddress((void**)&Wql, g_Wql);
    cudaGetSymbolAddress((void**)&Wkh, g_Wkh); cudaGetSymbolAddress((void**)&Wkl, g_Wkl);
    cudaGetSymbolAddress((void**)&Wvh, g_Wvh); cudaGetSymbolAddress((void**)&Wvl, g_Wvl);
    cudaGetSymbolAddress((void**)&Woh, g_Woh); cudaGetSymbolAddress((void**)&Wol, g_Wol);
    cudaGetSymbolAddress((void**)&Qh, g_Qh);   cudaGetSymbolAddress((void**)&Ql, g_Ql);
    cudaGetSymbolAddress((void**)&Kh, g_Kh);   cudaGetSymbolAddress((void**)&Kl, g_Kl);
    cudaGetSymbolAddress((void**)&Vh, g_Vh);   cudaGetSymbolAddress((void**)&Vl, g_Vl);
    cudaGetSymbolAddress((void**)&Ch, g_Ch);   cudaGetSymbolAddress((void**)&Cl, g_Cl);

    const int nX4 = MROWS * DIM / 4;    // 1048576
    const int nW4 = DIM * DIM / 4;      // 262144
    split_kernel<<<nX4 / 256, 256>>>((const float4*)X,  (__half2*)Xh,  (__half2*)Xl,  nX4);
    split_kernel<<<nW4 / 256, 256>>>((const float4*)Wq, (__half2*)Wqh, (__half2*)Wql, nW4);
    split_kernel<<<nW4 / 256, 256>>>((const float4*)Wk, (__half2*)Wkh, (__half2*)Wkl, nW4);
    split_kernel<<<nW4 / 256, 256>>>((const float4*)Wv, (__half2*)Wvh, (__half2*)Wvl, nW4);
    split_kernel<<<nW4 / 256, 256>>>((const float4*)Wo, (__half2*)Woh, (__half2*)Wol, nW4);

    dim3 ggrid(DIM / GBN, MROWS / GBM);  // (8, 64)
    gemmh_kernel<true><<<ggrid, 256>>>(Xh, Xl, Wqh, Wql, bq, 0.125f, nullptr, Qh, Ql);
    gemmh_kernel<true><<<ggrid, 256>>>(Xh, Xl, Wkh, Wkl, bk, 1.0f,   nullptr, Kh, Kl);
    gemmh_kernel<true><<<ggrid, 256>>>(Xh, Xl, Wvh, Wvl, bv, 1.0f,   nullptr, Vh, Vl);

    dim3 fgrid(SEQ / 128, NH, BATCH);    // (16, 16, 2)
    flash16_kernel<<<fgrid, 256>>>(Qh, Ql, Kh, Kl, Vh, Vl, mask, Ch, Cl);

    gemmh_kernel<false><<<ggrid, 256>>>(Ch, Cl, Woh, Wol, bo, 1.0f, out, nullptr, nullptr);
}